// round 11
// baseline (speedup 1.0000x reference)
#include <cuda_runtime.h>
#include <cuda_bf16.h>
#include <cstdint>
#include <math.h>

// Problem dims
#define Bv 128
#define Lv 512
#define Dv 512
#define Ev 64
#define Hv 512
#define Vv 17

#define FULLMASK 0xffffffffu

// Output layout (float32 concat of the 4 reference outputs)
#define OFF_LOGITS 0
#define OFF_PREDS  (Bv*Lv*Vv)                 // 1114112
#define OFF_PROBS  (OFF_PREDS + Bv*Lv)        // 1179648
#define OFF_EMB    (OFF_PROBS + Bv*Lv*Vv)     // 2293760

// Scratch: pre[b, t, h] = inputs[b,t,:] @ W1[:, :D]^T + b1   (128 MB)
__device__ float g_pre[(size_t)Bv * Lv * Hv];

// ---------------------------------------------------------------------------
__device__ __forceinline__ float lo_part(float x) {
    float h = __uint_as_float(__float_as_uint(x) & 0xFFFFE000u);
    return x - h;   // exact
}

__device__ __forceinline__ void mma_tf32(
    float* d, const uint32_t* a, const uint32_t* b)
{
    asm volatile(
        "mma.sync.aligned.m16n8k8.row.col.f32.tf32.tf32.f32 "
        "{%0,%1,%2,%3}, {%4,%5,%6,%7}, {%8,%9}, {%0,%1,%2,%3};\n"
        : "+f"(d[0]), "+f"(d[1]), "+f"(d[2]), "+f"(d[3])
        : "r"(a[0]), "r"(a[1]), "r"(a[2]), "r"(a[3]),
          "r"(b[0]), "r"(b[1]));
}

// dynamic smem layout in floats: A | B, 8192 floats each (64KB total), BK=64
#define F_A 0
#define F_B 8192
#define SM_TOT_BYTES (16384 * 4)

// ---------------------------------------------------------------------------
// Kernel 1: pre = A @ W1x^T + b1 via mma.sync tf32, 3-term precision split
// with hi/lo derived in registers (raw f32 in smem; HW truncates f32->tf32,
// lo = x - trunc(x)).  2048 CTAs x 256 threads, 128x128 tile, BK=64
// (8 chunks -> half the barriers of BK=32).
// Fragment-major smem layout so each fragment load is one LDS.128 / LDS.64:
//   A: [ks(8)][mf(8)][lane(32)][reg(4)]   (8192 floats)
//   B: [ks(8)][nf(16)][lane(32)][reg(2)]  (8192 floats)
// ---------------------------------------------------------------------------
__global__ __launch_bounds__(256) void gemm_mma_kernel(
    const float* __restrict__ A,      // [B*L, D]
    const float* __restrict__ W,      // [H, D+E]
    const float* __restrict__ bias)   // [H]
{
    extern __shared__ float sm[];

    const int tid  = threadIdx.x;
    const int w    = tid >> 5;
    const int lane = tid & 31;
    const int wm   = w >> 2;          // 0..1  (m offset 64)
    const int wn   = w & 3;           // 0..3  (n offset 32)

    const int bm = (blockIdx.x >> 2) * 128;   // row block in [B*L]
    const int bn = (blockIdx.x & 3) * 128;    // col block in [H]

    // staging mapping: thread t handles row = t>>1, k-cols cgrp..cgrp+31
    const int srow = tid >> 1;
    const int cgrp = (tid & 1) * 32;

    const float* aP = A + (size_t)(bm + srow) * Dv + cgrp;
    const float* wP = W + (size_t)(bn + srow) * (Dv + Ev) + cgrp;

    float acc[4][4][4];
#pragma unroll
    for (int i = 0; i < 4; i++)
#pragma unroll
        for (int j = 0; j < 4; j++)
#pragma unroll
            for (int r = 0; r < 4; r++) acc[i][j][r] = 0.f;

    // A-row scatter base pieces (row fixed per thread)
    const int a_mf  = srow >> 4;
    const int a_r16 = srow & 15;
    const int a_lb  = (a_r16 & 7) << 2;       // lane base (+= c&3)
    const int a_rb  = a_r16 >> 3;             // reg base  (+= 2*(c8>>2))
    // B-row scatter base pieces
    const int b_nf  = srow >> 3;
    const int b_lb  = (srow & 7) << 2;

    for (int ch = 0; ch < 8; ch++) {
        const int k0 = ch * 64;
        // ---- stage: load 32 A + 32 B floats, scatter raw f32 to frag layout
#pragma unroll
        for (int q = 0; q < 8; q++) {
            const int kc = cgrp + q * 4;          // chunk-local k col 0..63
            const int ks = kc >> 3;
            const int c8 = kc & 7;
            float4 av = *reinterpret_cast<const float4*>(aP + k0 + q * 4);
            float4 bv = *reinterpret_cast<const float4*>(wP + k0 + q * 4);

            // A scatter: idx = ((ks*8+mf)*32 + lane)*4 + reg, stride 4 per c
            {
                const int reg = a_rb + ((c8 >> 2) << 1);
                const int base = ((ks * 8 + a_mf) * 32 + a_lb + (c8 & 3)) * 4 + reg;
                sm[F_A + base]      = av.x;
                sm[F_A + base + 4]  = av.y;
                sm[F_A + base + 8]  = av.z;
                sm[F_A + base + 12] = av.w;
            }
            // B scatter: idx = ((ks*16+nf)*32 + lane)*2 + reg, lane += k&3
            {
                const int reg = c8 >> 2;
                const int base = ((ks * 16 + b_nf) * 32 + b_lb + (c8 & 3)) * 2 + reg;
                sm[F_B + base]     = bv.x;
                sm[F_B + base + 2] = bv.y;
                sm[F_B + base + 4] = bv.z;
                sm[F_B + base + 6] = bv.w;
            }
        }
        __syncthreads();

        // ---- compute: 8 k-steps ----
#pragma unroll
        for (int ks = 0; ks < 8; ks++) {
            float    afr[4][4];
            uint32_t alo[4][4];
            float    bfr[4][2];
            uint32_t blo[4][2];
#pragma unroll
            for (int mf = 0; mf < 4; mf++) {
                const int mfg = wm * 4 + mf;
                const int ix = ((ks * 8 + mfg) * 32 + lane) * 4;
                *reinterpret_cast<float4*>(afr[mf]) =
                    *reinterpret_cast<const float4*>(&sm[F_A + ix]);
#pragma unroll
                for (int r = 0; r < 4; r++)
                    alo[mf][r] = __float_as_uint(lo_part(afr[mf][r]));
            }
#pragma unroll
            for (int nf = 0; nf < 4; nf++) {
                const int nfg = wn * 4 + nf;
                const int ix = ((ks * 16 + nfg) * 32 + lane) * 2;
                *reinterpret_cast<float2*>(bfr[nf]) =
                    *reinterpret_cast<const float2*>(&sm[F_B + ix]);
#pragma unroll
                for (int r = 0; r < 2; r++)
                    blo[nf][r] = __float_as_uint(lo_part(bfr[nf][r]));
            }
#pragma unroll
            for (int mf = 0; mf < 4; mf++)
#pragma unroll
                for (int nf = 0; nf < 4; nf++) {
                    const uint32_t* ahi =
                        reinterpret_cast<const uint32_t*>(afr[mf]);
                    const uint32_t* bhi =
                        reinterpret_cast<const uint32_t*>(bfr[nf]);
                    mma_tf32(acc[mf][nf], ahi, bhi);
                    mma_tf32(acc[mf][nf], ahi, blo[nf]);
                    mma_tf32(acc[mf][nf], alo[mf], bhi);
                }
        }
        __syncthreads();
    }

    // ---- epilogue ----
#pragma unroll
    for (int mf = 0; mf < 4; mf++) {
        const int row0 = bm + wm * 64 + mf * 16 + (lane >> 2);
#pragma unroll
        for (int nf = 0; nf < 4; nf++) {
            const int col0 = bn + wn * 32 + nf * 8 + 2 * (lane & 3);
            const float bb0 = bias[col0];
            const float bb1 = bias[col0 + 1];
            float2 v0, v1;
            v0.x = acc[mf][nf][0] + bb0;
            v0.y = acc[mf][nf][1] + bb1;
            v1.x = acc[mf][nf][2] + bb0;
            v1.y = acc[mf][nf][3] + bb1;
            *reinterpret_cast<float2*>(&g_pre[(size_t)row0 * Hv + col0]) = v0;
            *reinterpret_cast<float2*>(&g_pre[(size_t)(row0 + 8) * Hv + col0]) = v1;
        }
    }
}

// ---------------------------------------------------------------------------
// fast warp argmax over lanes [0, Vv): monotone-uint transform + redux.max +
// ballot + ffs.  Uniform across the warp; first-max tie-break (jnp.argmax).
// ---------------------------------------------------------------------------
__device__ __forceinline__ int argmax17(float v, int lane)
{
    unsigned u = __float_as_uint(v);
    u = (u & 0x80000000u) ? ~u : (u | 0x80000000u);
    if (lane >= Vv) u = 0u;
    unsigned mx = __reduce_max_sync(FULLMASK, u);
    unsigned msk = __ballot_sync(FULLMASK, u == mx);
    return __ffs(msk) - 1;
}

// ---------------------------------------------------------------------------
// Kernel 2: sequential scan. 1 CTA per batch element, 512 threads (16 warps,
// balanced 4/4/4/4 across SMSPs). Warp w computes logit w; warp 15 also
// computes logit 16 (reusing its sH fragment loads). Stage-B sH reads are
// 4x LDS.128 per warp (lane reads sH[lane*16 .. lane*16+15]).
// ---------------------------------------------------------------------------
__global__ __launch_bounds__(512) void scan_kernel(
    const float* __restrict__ emb_table,   // [V, E]
    const float* __restrict__ W1,          // [H, D+E]
    const float* __restrict__ W2,          // [V, H]
    const float* __restrict__ b2,          // [V]
    float* __restrict__ out)
{
    __shared__ float sM[Vv][Hv];
    __shared__ float sH[Hv];
    __shared__ float sLogit[20];

    const int b    = blockIdx.x;
    const int tid  = threadIdx.x;
    const int w    = tid >> 5;
    const int lane = tid & 31;

    for (int idx = tid; idx < Vv * Hv; idx += 512) {
        int v = idx / Hv, h = idx - v * Hv;
        float acc = 0.f;
        if (v != 0) {
            const float* er = emb_table + v * Ev;
            const float* wr = W1 + (size_t)h * (Dv + Ev) + Dv;
#pragma unroll 8
            for (int e = 0; e < Ev; e++) acc += er[e] * wr[e];
        }
        sM[v][h] = acc;
    }

    // W2 in registers, fragment order: w2q[j] = W2[w][lane*16 + j*4 .. +3]
    float4 w2q[4];
    {
        const float4* p = reinterpret_cast<const float4*>(
            &W2[(size_t)w * Hv + lane * 16]);
#pragma unroll
        for (int j = 0; j < 4; j++) w2q[j] = p[j];
    }
    const float bias2 = b2[w];
    // warp 15 additionally owns logit 16
    float4 w2qB[4];
    float bias2B = 0.f;
    if (w == 15) {
        const float4* p = reinterpret_cast<const float4*>(
            &W2[(size_t)16 * Hv + lane * 16]);
#pragma unroll
        for (int j = 0; j < 4; j++) w2qB[j] = p[j];
        bias2B = b2[16];
    }
    __syncthreads();

    float* outL = out + OFF_LOGITS;
    float* outP = out + OFF_PREDS;

    const float* preB = g_pre + (size_t)b * Lv * Hv;

    float pcur = preB[tid];

    for (int t = 0; t < Lv; t++) {
        float pnxt = 0.f;
        if (t + 1 < Lv) pnxt = preB[(size_t)(t + 1) * Hv + tid];

        // stage A: every warp computes argmax of previous logits, then hidden
        int pred;
        if (t == 0) {
            pred = 0;   // PAD
        } else {
            pred = argmax17((lane < Vv) ? sLogit[lane] : 0.f, lane);
            if (tid == 0) outP[(size_t)b * Lv + (t - 1)] = (float)pred;
        }
        sH[tid] = tanhf(pcur + sM[pred][tid]);
        __syncthreads();

        // stage B: warp w computes logit w (warp 15 also logit 16)
        {
            const float4* hp = reinterpret_cast<const float4*>(&sH[lane * 16]);
            float4 h0 = hp[0], h1 = hp[1], h2 = hp[2], h3 = hp[3];
            float a0 = h0.x * w2q[0].x + h0.y * w2q[0].y
                     + h0.z * w2q[0].z + h0.w * w2q[0].w;
            float a1 = h1.x * w2q[1].x + h1.y * w2q[1].y
                     + h1.z * w2q[1].z + h1.w * w2q[1].w;
            float a2 = h2.x * w2q[2].x + h2.y * w2q[2].y
                     + h2.z * w2q[2].z + h2.w * w2q[2].w;
            float a3 = h3.x * w2q[3].x + h3.y * w2q[3].y
                     + h3.z * w2q[3].z + h3.w * w2q[3].w;
            float acc = (a0 + a1) + (a2 + a3);

            float accB = 0.f;
            if (w == 15) {
                float c0 = h0.x * w2qB[0].x + h0.y * w2qB[0].y
                         + h0.z * w2qB[0].z + h0.w * w2qB[0].w;
                float c1 = h1.x * w2qB[1].x + h1.y * w2qB[1].y
                         + h1.z * w2qB[1].z + h1.w * w2qB[1].w;
                float c2 = h2.x * w2qB[2].x + h2.y * w2qB[2].y
                         + h2.z * w2qB[2].z + h2.w * w2qB[2].w;
                float c3 = h3.x * w2qB[3].x + h3.y * w2qB[3].y
                         + h3.z * w2qB[3].z + h3.w * w2qB[3].w;
                accB = (c0 + c1) + (c2 + c3);
            }
#pragma unroll
            for (int off = 16; off; off >>= 1) {
                acc  += __shfl_xor_sync(FULLMASK, acc, off);
                accB += __shfl_xor_sync(FULLMASK, accB, off);
            }
            if (lane == 0) {
                float lg = acc + bias2;
                sLogit[w] = lg;
                outL[((size_t)b * Lv + t) * Vv + w] = lg;
                if (w == 15) {
                    float lgB = accB + bias2B;
                    sLogit[16] = lgB;
                    outL[((size_t)b * Lv + t) * Vv + 16] = lgB;
                }
            }
        }
        __syncthreads();

        pcur = pnxt;
    }

    // tail: argmax for the final timestep
    if (w == 0) {
        int pred = argmax17((lane < Vv) ? sLogit[lane] : 0.f, lane);
        if (lane == 0) outP[(size_t)b * Lv + (Lv - 1)] = (float)pred;
    }
}

// ---------------------------------------------------------------------------
// Kernel 3: parallel post-pass — log-softmax from saved logits, preds_emb.
// ---------------------------------------------------------------------------
__global__ __launch_bounds__(256) void post_kernel(
    const float* __restrict__ emb_table,
    float* __restrict__ out)
{
    const float* outL = out + OFF_LOGITS;
    const float* outP = out + OFF_PREDS;
    float* outQ  = out + OFF_PROBS;
    float* outEb = out + OFF_EMB;

    const int lane = threadIdx.x & 31;
    const int warps_total = (gridDim.x * blockDim.x) >> 5;
    int gw = (blockIdx.x * blockDim.x + threadIdx.x) >> 5;

    for (int row = gw; row < Bv * Lv; row += warps_total) {
        float v = (lane < Vv) ? outL[(size_t)row * Vv + lane] : -1e30f;
        float m = v;
#pragma unroll
        for (int off = 16; off; off >>= 1)
            m = fmaxf(m, __shfl_xor_sync(FULLMASK, m, off));
        float e = (lane < Vv) ? expf(v - m) : 0.f;
        float s = e;
#pragma unroll
        for (int off = 16; off; off >>= 1)
            s += __shfl_xor_sync(FULLMASK, s, off);
        float lse = m + logf(s);
        if (lane < Vv) outQ[(size_t)row * Vv + lane] = v - lse;

        int pred = (int)outP[row];
        float e0 = (pred != 0) ? emb_table[pred * Ev + lane] : 0.f;
        float e1 = (pred != 0) ? emb_table[pred * Ev + 32 + lane] : 0.f;
        outEb[(size_t)row * Ev + lane]      = e0;
        outEb[(size_t)row * Ev + 32 + lane] = e1;
    }
}

// ---------------------------------------------------------------------------
extern "C" void kernel_launch(void* const* d_in, const int* in_sizes, int n_in,
                              void* d_out, int out_size)
{
    const float* inputs    = (const float*)d_in[0];  // [B, L, D]
    const float* emb_table = (const float*)d_in[1];  // [V, E]
    const float* W1        = (const float*)d_in[2];  // [H, D+E]
    const float* b1        = (const float*)d_in[3];  // [H]
    const float* W2        = (const float*)d_in[4];  // [V, H]
    const float* b2        = (const float*)d_in[5];  // [V]
    float* out = (float*)d_out;

    (void)in_sizes; (void)n_in; (void)out_size;

    cudaFuncSetAttribute(gemm_mma_kernel,
                         cudaFuncAttributeMaxDynamicSharedMemorySize,
                         SM_TOT_BYTES);

    gemm_mma_kernel<<<2048, 256, SM_TOT_BYTES>>>(inputs, W1, b1);

    scan_kernel<<<Bv, 512>>>(emb_table, W1, W2, b2, out);

    post_kernel<<<256, 256>>>(emb_table, out);
}

// round 12
// speedup vs baseline: 1.9945x; 1.9945x over previous
#include <cuda_runtime.h>
#include <cuda_bf16.h>
#include <cstdint>
#include <math.h>

// Problem dims
#define Bv 128
#define Lv 512
#define Dv 512
#define Ev 64
#define Hv 512
#define Vv 17

#define FULLMASK 0xffffffffu

// Output layout (float32 concat of the 4 reference outputs)
#define OFF_LOGITS 0
#define OFF_PREDS  (Bv*Lv*Vv)                 // 1114112
#define OFF_PROBS  (OFF_PREDS + Bv*Lv)        // 1179648
#define OFF_EMB    (OFF_PROBS + Bv*Lv*Vv)     // 2293760

// Scratch: pre[b, t, h] = inputs[b,t,:] @ W1[:, :D]^T + b1   (128 MB)
__device__ float g_pre[(size_t)Bv * Lv * Hv];

// ---------------------------------------------------------------------------
__device__ __forceinline__ float lo_part(float x) {
    float h = __uint_as_float(__float_as_uint(x) & 0xFFFFE000u);
    return x - h;   // exact
}

__device__ __forceinline__ void mma_tf32(
    float* d, const uint32_t* a, const uint32_t* b)
{
    asm volatile(
        "mma.sync.aligned.m16n8k8.row.col.f32.tf32.tf32.f32 "
        "{%0,%1,%2,%3}, {%4,%5,%6,%7}, {%8,%9}, {%0,%1,%2,%3};\n"
        : "+f"(d[0]), "+f"(d[1]), "+f"(d[2]), "+f"(d[3])
        : "r"(a[0]), "r"(a[1]), "r"(a[2]), "r"(a[3]),
          "r"(b[0]), "r"(b[1]));
}

// dynamic smem layout in floats: A | B, 4096 floats each (32KB total), BK=32
#define F_A 0
#define F_B 4096
#define SM_TOT_BYTES (8192 * 4)

// ---------------------------------------------------------------------------
// Kernel 1: pre = A @ W1x^T + b1 via mma.sync tf32, 3-term precision split
// with hi/lo derived in registers (raw f32 in smem; HW truncates f32->tf32,
// lo = x - trunc(x)).  2048 CTAs x 256 threads, 128x128 tile, BK=32.
// (Exact R10 configuration — 634us, tensor 53%.)
// Fragment-major smem layout so each fragment load is one LDS.128 / LDS.64:
//   A: [ks(4)][mf(8)][lane(32)][reg(4)]   (4096 floats)
//   B: [ks(4)][nf(16)][lane(32)][reg(2)]  (4096 floats)
// ---------------------------------------------------------------------------
__global__ __launch_bounds__(256) void gemm_mma_kernel(
    const float* __restrict__ A,      // [B*L, D]
    const float* __restrict__ W,      // [H, D+E]
    const float* __restrict__ bias)   // [H]
{
    extern __shared__ float sm[];

    const int tid  = threadIdx.x;
    const int w    = tid >> 5;
    const int lane = tid & 31;
    const int wm   = w >> 2;          // 0..1  (m offset 64)
    const int wn   = w & 3;           // 0..3  (n offset 32)

    const int bm = (blockIdx.x >> 2) * 128;   // row block in [B*L]
    const int bn = (blockIdx.x & 3) * 128;    // col block in [H]

    // staging mapping: thread t handles row = t>>1, k-cols cgrp..cgrp+15
    const int srow = tid >> 1;
    const int cgrp = (tid & 1) * 16;

    const float* aP = A + (size_t)(bm + srow) * Dv + cgrp;
    const float* wP = W + (size_t)(bn + srow) * (Dv + Ev) + cgrp;

    float acc[4][4][4];
#pragma unroll
    for (int i = 0; i < 4; i++)
#pragma unroll
        for (int j = 0; j < 4; j++)
#pragma unroll
            for (int r = 0; r < 4; r++) acc[i][j][r] = 0.f;

    // A-row scatter base pieces (row fixed per thread)
    const int a_mf  = srow >> 4;
    const int a_r16 = srow & 15;
    const int a_lb  = (a_r16 & 7) << 2;       // lane base (+= c&3)
    const int a_rb  = a_r16 >> 3;             // reg base  (+= 2*(c8>>2))
    // B-row scatter base pieces
    const int b_nf  = srow >> 3;
    const int b_lb  = (srow & 7) << 2;

    for (int ch = 0; ch < 16; ch++) {
        const int k0 = ch * 32;
        // ---- stage: load 16 A + 16 B floats, scatter raw f32 to frag layout
#pragma unroll
        for (int q = 0; q < 4; q++) {
            const int kc = cgrp + q * 4;          // chunk-local k col
            const int ks = kc >> 3;
            const int c8 = kc & 7;
            float4 av = *reinterpret_cast<const float4*>(aP + k0 + q * 4);
            float4 bv = *reinterpret_cast<const float4*>(wP + k0 + q * 4);

            // A scatter: idx = ((ks*8+mf)*32 + lane)*4 + reg, stride 4 per c
            {
                const int reg = a_rb + ((c8 >> 2) << 1);
                const int base = ((ks * 8 + a_mf) * 32 + a_lb + (c8 & 3)) * 4 + reg;
                sm[F_A + base]      = av.x;
                sm[F_A + base + 4]  = av.y;
                sm[F_A + base + 8]  = av.z;
                sm[F_A + base + 12] = av.w;
            }
            // B scatter: idx = ((ks*16+nf)*32 + lane)*2 + reg, lane += k&3
            {
                const int reg = c8 >> 2;
                const int base = ((ks * 16 + b_nf) * 32 + b_lb + (c8 & 3)) * 2 + reg;
                sm[F_B + base]     = bv.x;
                sm[F_B + base + 2] = bv.y;
                sm[F_B + base + 4] = bv.z;
                sm[F_B + base + 6] = bv.w;
            }
        }
        __syncthreads();

        // ---- compute: 4 k-steps ----
#pragma unroll
        for (int ks = 0; ks < 4; ks++) {
            float    afr[4][4];
            uint32_t alo[4][4];
            float    bfr[4][2];
            uint32_t blo[4][2];
#pragma unroll
            for (int mf = 0; mf < 4; mf++) {
                const int mfg = wm * 4 + mf;
                const int ix = ((ks * 8 + mfg) * 32 + lane) * 4;
                *reinterpret_cast<float4*>(afr[mf]) =
                    *reinterpret_cast<const float4*>(&sm[F_A + ix]);
#pragma unroll
                for (int r = 0; r < 4; r++)
                    alo[mf][r] = __float_as_uint(lo_part(afr[mf][r]));
            }
#pragma unroll
            for (int nf = 0; nf < 4; nf++) {
                const int nfg = wn * 4 + nf;
                const int ix = ((ks * 16 + nfg) * 32 + lane) * 2;
                *reinterpret_cast<float2*>(bfr[nf]) =
                    *reinterpret_cast<const float2*>(&sm[F_B + ix]);
#pragma unroll
                for (int r = 0; r < 2; r++)
                    blo[nf][r] = __float_as_uint(lo_part(bfr[nf][r]));
            }
#pragma unroll
            for (int mf = 0; mf < 4; mf++)
#pragma unroll
                for (int nf = 0; nf < 4; nf++) {
                    const uint32_t* ahi =
                        reinterpret_cast<const uint32_t*>(afr[mf]);
                    const uint32_t* bhi =
                        reinterpret_cast<const uint32_t*>(bfr[nf]);
                    mma_tf32(acc[mf][nf], ahi, bhi);
                    mma_tf32(acc[mf][nf], ahi, blo[nf]);
                    mma_tf32(acc[mf][nf], alo[mf], bhi);
                }
        }
        __syncthreads();
    }

    // ---- epilogue ----
#pragma unroll
    for (int mf = 0; mf < 4; mf++) {
        const int row0 = bm + wm * 64 + mf * 16 + (lane >> 2);
#pragma unroll
        for (int nf = 0; nf < 4; nf++) {
            const int col0 = bn + wn * 32 + nf * 8 + 2 * (lane & 3);
            const float bb0 = bias[col0];
            const float bb1 = bias[col0 + 1];
            float2 v0, v1;
            v0.x = acc[mf][nf][0] + bb0;
            v0.y = acc[mf][nf][1] + bb1;
            v1.x = acc[mf][nf][2] + bb0;
            v1.y = acc[mf][nf][3] + bb1;
            *reinterpret_cast<float2*>(&g_pre[(size_t)row0 * Hv + col0]) = v0;
            *reinterpret_cast<float2*>(&g_pre[(size_t)(row0 + 8) * Hv + col0]) = v1;
        }
    }
}

// ---------------------------------------------------------------------------
// fast warp argmax over lanes [0, Vv): monotone-uint transform + redux.max +
// ballot + ffs.  Uniform across the warp; first-max tie-break (jnp.argmax).
// ---------------------------------------------------------------------------
__device__ __forceinline__ int argmax17(float v, int lane)
{
    unsigned u = __float_as_uint(v);
    u = (u & 0x80000000u) ? ~u : (u | 0x80000000u);
    if (lane >= Vv) u = 0u;
    unsigned mx = __reduce_max_sync(FULLMASK, u);
    unsigned msk = __ballot_sync(FULLMASK, u == mx);
    return __ffs(msk) - 1;
}

// ---------------------------------------------------------------------------
// Kernel 2: sequential scan. 1 CTA per batch element, 512 threads (16 warps,
// balanced 4/4/4/4 per SMSP). Warp w computes logit w; warp 15 also computes
// logit 16, reusing its (conflict-free, scalar) sH loads. Softmax/embedding
// deferred to post_kernel.
// ---------------------------------------------------------------------------
__global__ __launch_bounds__(512) void scan_kernel(
    const float* __restrict__ emb_table,   // [V, E]
    const float* __restrict__ W1,          // [H, D+E]
    const float* __restrict__ W2,          // [V, H]
    const float* __restrict__ b2,          // [V]
    float* __restrict__ out)
{
    __shared__ float sM[Vv][Hv];
    __shared__ float sH[Hv];
    __shared__ float sLogit[20];

    const int b    = blockIdx.x;
    const int tid  = threadIdx.x;
    const int w    = tid >> 5;
    const int lane = tid & 31;

    for (int idx = tid; idx < Vv * Hv; idx += 512) {
        int v = idx / Hv, h = idx - v * Hv;
        float acc = 0.f;
        if (v != 0) {
            const float* er = emb_table + v * Ev;
            const float* wr = W1 + (size_t)h * (Dv + Ev) + Dv;
#pragma unroll 8
            for (int e = 0; e < 64; e++) acc += er[e] * wr[e];
        }
        sM[v][h] = acc;
    }

    // W2 rows in registers (R10 conflict-free layout): w2r[k]=W2[w][k*32+lane]
    float w2r[16];
#pragma unroll
    for (int k = 0; k < 16; k++) w2r[k] = W2[(size_t)w * Hv + k * 32 + lane];
    const float bias2 = b2[w];
    // warp 15 additionally owns logit 16
    float w2rB[16];
    float bias2B = 0.f;
    if (w == 15) {
#pragma unroll
        for (int k = 0; k < 16; k++)
            w2rB[k] = W2[(size_t)16 * Hv + k * 32 + lane];
        bias2B = b2[16];
    }
    __syncthreads();

    float* outL = out + OFF_LOGITS;
    float* outP = out + OFF_PREDS;

    const float* preB = g_pre + (size_t)b * Lv * Hv;

    float pcur = preB[tid];

    for (int t = 0; t < Lv; t++) {
        float pnxt = 0.f;
        if (t + 1 < Lv) pnxt = preB[(size_t)(t + 1) * Hv + tid];

        // stage A: every warp computes argmax of previous logits, then hidden
        int pred;
        if (t == 0) {
            pred = 0;   // PAD
        } else {
            pred = argmax17((lane < Vv) ? sLogit[lane] : 0.f, lane);
            if (tid == 0) outP[(size_t)b * Lv + (t - 1)] = (float)pred;
        }
        sH[tid] = tanhf(pcur + sM[pred][tid]);
        __syncthreads();

        // stage B: warp w computes logit w (warp 15 also logit 16)
        {
            float hv[16];
#pragma unroll
            for (int k = 0; k < 16; k++) hv[k] = sH[k * 32 + lane];

            float acc = 0.f;
#pragma unroll
            for (int k = 0; k < 16; k++) acc += hv[k] * w2r[k];
#pragma unroll
            for (int off = 16; off; off >>= 1)
                acc += __shfl_xor_sync(FULLMASK, acc, off);
            if (lane == 0) {
                float lg = acc + bias2;
                sLogit[w] = lg;
                outL[((size_t)b * Lv + t) * Vv + w] = lg;
            }

            if (w == 15) {
                float accB = 0.f;
#pragma unroll
                for (int k = 0; k < 16; k++) accB += hv[k] * w2rB[k];
#pragma unroll
                for (int off = 16; off; off >>= 1)
                    accB += __shfl_xor_sync(FULLMASK, accB, off);
                if (lane == 0) {
                    float lgB = accB + bias2B;
                    sLogit[16] = lgB;
                    outL[((size_t)b * Lv + t) * Vv + 16] = lgB;
                }
            }
        }
        __syncthreads();

        pcur = pnxt;
    }

    // tail: argmax for the final timestep
    if (w == 0) {
        int pred = argmax17((lane < Vv) ? sLogit[lane] : 0.f, lane);
        if (lane == 0) outP[(size_t)b * Lv + (Lv - 1)] = (float)pred;
    }
}

// ---------------------------------------------------------------------------
// Kernel 3: parallel post-pass — log-softmax from saved logits, preds_emb.
// ---------------------------------------------------------------------------
__global__ __launch_bounds__(256) void post_kernel(
    const float* __restrict__ emb_table,
    float* __restrict__ out)
{
    const float* outL = out + OFF_LOGITS;
    const float* outP = out + OFF_PREDS;
    float* outQ  = out + OFF_PROBS;
    float* outEb = out + OFF_EMB;

    const int lane = threadIdx.x & 31;
    const int warps_total = (gridDim.x * blockDim.x) >> 5;
    int gw = (blockIdx.x * blockDim.x + threadIdx.x) >> 5;

    for (int row = gw; row < Bv * Lv; row += warps_total) {
        float v = (lane < Vv) ? outL[(size_t)row * Vv + lane] : -1e30f;
        float m = v;
#pragma unroll
        for (int off = 16; off; off >>= 1)
            m = fmaxf(m, __shfl_xor_sync(FULLMASK, m, off));
        float e = (lane < Vv) ? expf(v - m) : 0.f;
        float s = e;
#pragma unroll
        for (int off = 16; off; off >>= 1)
            s += __shfl_xor_sync(FULLMASK, s, off);
        float lse = m + logf(s);
        if (lane < Vv) outQ[(size_t)row * Vv + lane] = v - lse;

        int pred = (int)outP[row];
        float e0 = (pred != 0) ? emb_table[pred * Ev + lane] : 0.f;
        float e1 = (pred != 0) ? emb_table[pred * Ev + 32 + lane] : 0.f;
        outEb[(size_t)row * Ev + lane]      = e0;
        outEb[(size_t)row * Ev + 32 + lane] = e1;
    }
}

// ---------------------------------------------------------------------------
extern "C" void kernel_launch(void* const* d_in, const int* in_sizes, int n_in,
                              void* d_out, int out_size)
{
    const float* inputs    = (const float*)d_in[0];  // [B, L, D]
    const float* emb_table = (const float*)d_in[1];  // [V, E]
    const float* W1        = (const float*)d_in[2];  // [H, D+E]
    const float* b1        = (const float*)d_in[3];  // [H]
    const float* W2        = (const float*)d_in[4];  // [V, H]
    const float* b2        = (const float*)d_in[5];  // [V]
    float* out = (float*)d_out;

    (void)in_sizes; (void)n_in; (void)out_size;

    cudaFuncSetAttribute(gemm_mma_kernel,
                         cudaFuncAttributeMaxDynamicSharedMemorySize,
                         SM_TOT_BYTES);

    gemm_mma_kernel<<<2048, 256, SM_TOT_BYTES>>>(inputs, W1, b1);

    scan_kernel<<<Bv, 512>>>(emb_table, W1, W2, b2, out);

    post_kernel<<<256, 256>>>(emb_table, out);
}

// round 13
// speedup vs baseline: 2.0058x; 1.0057x over previous
#include <cuda_runtime.h>
#include <cuda_bf16.h>
#include <cstdint>
#include <math.h>

// Problem dims
#define Bv 128
#define Lv 512
#define Dv 512
#define Ev 64
#define Hv 512
#define Vv 17

#define FULLMASK 0xffffffffu

// Output layout (float32 concat of the 4 reference outputs)
#define OFF_LOGITS 0
#define OFF_PREDS  (Bv*Lv*Vv)                 // 1114112
#define OFF_PROBS  (OFF_PREDS + Bv*Lv)        // 1179648
#define OFF_EMB    (OFF_PROBS + Bv*Lv*Vv)     // 2293760

// Scratch: pre[b, t, h] = inputs[b,t,:] @ W1[:, :D]^T + b1   (128 MB)
__device__ float g_pre[(size_t)Bv * Lv * Hv];

// ---------------------------------------------------------------------------
__device__ __forceinline__ float lo_part(float x) {
    float h = __uint_as_float(__float_as_uint(x) & 0xFFFFE000u);
    return x - h;   // exact
}

__device__ __forceinline__ void mma_tf32(
    float* d, const uint32_t* a, const uint32_t* b)
{
    asm volatile(
        "mma.sync.aligned.m16n8k8.row.col.f32.tf32.tf32.f32 "
        "{%0,%1,%2,%3}, {%4,%5,%6,%7}, {%8,%9}, {%0,%1,%2,%3};\n"
        : "+f"(d[0]), "+f"(d[1]), "+f"(d[2]), "+f"(d[3])
        : "r"(a[0]), "r"(a[1]), "r"(a[2]), "r"(a[3]),
          "r"(b[0]), "r"(b[1]));
}

// dynamic smem layout in floats: A | B, 4096 floats each (32KB total), BK=32
#define F_A 0
#define F_B 4096
#define SM_TOT_BYTES (8192 * 4)

// ---------------------------------------------------------------------------
// Kernel 1: pre = A @ W1x^T + b1 via mma.sync tf32, 3-term precision split
// with hi/lo derived in registers.  Exact R10 configuration (634us).
// ---------------------------------------------------------------------------
__global__ __launch_bounds__(256) void gemm_mma_kernel(
    const float* __restrict__ A,      // [B*L, D]
    const float* __restrict__ W,      // [H, D+E]
    const float* __restrict__ bias)   // [H]
{
    extern __shared__ float sm[];

    const int tid  = threadIdx.x;
    const int w    = tid >> 5;
    const int lane = tid & 31;
    const int wm   = w >> 2;          // 0..1  (m offset 64)
    const int wn   = w & 3;           // 0..3  (n offset 32)

    const int bm = (blockIdx.x >> 2) * 128;   // row block in [B*L]
    const int bn = (blockIdx.x & 3) * 128;    // col block in [H]

    const int srow = tid >> 1;
    const int cgrp = (tid & 1) * 16;

    const float* aP = A + (size_t)(bm + srow) * Dv + cgrp;
    const float* wP = W + (size_t)(bn + srow) * (Dv + Ev) + cgrp;

    float acc[4][4][4];
#pragma unroll
    for (int i = 0; i < 4; i++)
#pragma unroll
        for (int j = 0; j < 4; j++)
#pragma unroll
            for (int r = 0; r < 4; r++) acc[i][j][r] = 0.f;

    const int a_mf  = srow >> 4;
    const int a_r16 = srow & 15;
    const int a_lb  = (a_r16 & 7) << 2;
    const int a_rb  = a_r16 >> 3;
    const int b_nf  = srow >> 3;
    const int b_lb  = (srow & 7) << 2;

    for (int ch = 0; ch < 16; ch++) {
        const int k0 = ch * 32;
#pragma unroll
        for (int q = 0; q < 4; q++) {
            const int kc = cgrp + q * 4;
            const int ks = kc >> 3;
            const int c8 = kc & 7;
            float4 av = *reinterpret_cast<const float4*>(aP + k0 + q * 4);
            float4 bv = *reinterpret_cast<const float4*>(wP + k0 + q * 4);
            {
                const int reg = a_rb + ((c8 >> 2) << 1);
                const int base = ((ks * 8 + a_mf) * 32 + a_lb + (c8 & 3)) * 4 + reg;
                sm[F_A + base]      = av.x;
                sm[F_A + base + 4]  = av.y;
                sm[F_A + base + 8]  = av.z;
                sm[F_A + base + 12] = av.w;
            }
            {
                const int reg = c8 >> 2;
                const int base = ((ks * 16 + b_nf) * 32 + b_lb + (c8 & 3)) * 2 + reg;
                sm[F_B + base]     = bv.x;
                sm[F_B + base + 2] = bv.y;
                sm[F_B + base + 4] = bv.z;
                sm[F_B + base + 6] = bv.w;
            }
        }
        __syncthreads();

#pragma unroll
        for (int ks = 0; ks < 4; ks++) {
            float    afr[4][4];
            uint32_t alo[4][4];
            float    bfr[4][2];
            uint32_t blo[4][2];
#pragma unroll
            for (int mf = 0; mf < 4; mf++) {
                const int mfg = wm * 4 + mf;
                const int ix = ((ks * 8 + mfg) * 32 + lane) * 4;
                *reinterpret_cast<float4*>(afr[mf]) =
                    *reinterpret_cast<const float4*>(&sm[F_A + ix]);
#pragma unroll
                for (int r = 0; r < 4; r++)
                    alo[mf][r] = __float_as_uint(lo_part(afr[mf][r]));
            }
#pragma unroll
            for (int nf = 0; nf < 4; nf++) {
                const int nfg = wn * 4 + nf;
                const int ix = ((ks * 16 + nfg) * 32 + lane) * 2;
                *reinterpret_cast<float2*>(bfr[nf]) =
                    *reinterpret_cast<const float2*>(&sm[F_B + ix]);
#pragma unroll
                for (int r = 0; r < 2; r++)
                    blo[nf][r] = __float_as_uint(lo_part(bfr[nf][r]));
            }
#pragma unroll
            for (int mf = 0; mf < 4; mf++)
#pragma unroll
                for (int nf = 0; nf < 4; nf++) {
                    const uint32_t* ahi =
                        reinterpret_cast<const uint32_t*>(afr[mf]);
                    const uint32_t* bhi =
                        reinterpret_cast<const uint32_t*>(bfr[nf]);
                    mma_tf32(acc[mf][nf], ahi, bhi);
                    mma_tf32(acc[mf][nf], ahi, blo[nf]);
                    mma_tf32(acc[mf][nf], alo[mf], bhi);
                }
        }
        __syncthreads();
    }

#pragma unroll
    for (int mf = 0; mf < 4; mf++) {
        const int row0 = bm + wm * 64 + mf * 16 + (lane >> 2);
#pragma unroll
        for (int nf = 0; nf < 4; nf++) {
            const int col0 = bn + wn * 32 + nf * 8 + 2 * (lane & 3);
            const float bb0 = bias[col0];
            const float bb1 = bias[col0 + 1];
            float2 v0, v1;
            v0.x = acc[mf][nf][0] + bb0;
            v0.y = acc[mf][nf][1] + bb1;
            v1.x = acc[mf][nf][2] + bb0;
            v1.y = acc[mf][nf][3] + bb1;
            *reinterpret_cast<float2*>(&g_pre[(size_t)row0 * Hv + col0]) = v0;
            *reinterpret_cast<float2*>(&g_pre[(size_t)(row0 + 8) * Hv + col0]) = v1;
        }
    }
}

// ---------------------------------------------------------------------------
// fast warp argmax over lanes [0, Vv): monotone-uint transform + redux.max +
// ballot + ffs.  Uniform across the warp; first-max tie-break (jnp.argmax).
// ---------------------------------------------------------------------------
__device__ __forceinline__ int argmax17(float v, int lane)
{
    unsigned u = __float_as_uint(v);
    u = (u & 0x80000000u) ? ~u : (u | 0x80000000u);
    if (lane >= Vv) u = 0u;
    unsigned mx = __reduce_max_sync(FULLMASK, u);
    unsigned msk = __ballot_sync(FULLMASK, u == mx);
    return __ffs(msk) - 1;
}

// ---------------------------------------------------------------------------
// Kernel 2: sequential scan. 1 CTA per batch element, 256 threads (8 warps,
// 2/SMSP). Each thread owns h-elements {tid, tid+256}. Warp w computes
// logits {w, w+8} from one set of 16 conflict-free scalar sH loads; warp 0
// also computes logit 16. Softmax/embedding deferred to post_kernel.
// ---------------------------------------------------------------------------
__global__ __launch_bounds__(256) void scan_kernel(
    const float* __restrict__ emb_table,   // [V, E]
    const float* __restrict__ W1,          // [H, D+E]
    const float* __restrict__ W2,          // [V, H]
    const float* __restrict__ b2,          // [V]
    float* __restrict__ out)
{
    __shared__ float sM[Vv][Hv];
    __shared__ float sH[Hv];
    __shared__ float sLogit[20];

    const int b    = blockIdx.x;
    const int tid  = threadIdx.x;
    const int w    = tid >> 5;
    const int lane = tid & 31;

    for (int idx = tid; idx < Vv * Hv; idx += 256) {
        int v = idx / Hv, h = idx - v * Hv;
        float acc = 0.f;
        if (v != 0) {
            const float* er = emb_table + v * Ev;
            const float* wr = W1 + (size_t)h * (Dv + Ev) + Dv;
#pragma unroll 8
            for (int e = 0; e < Ev; e++) acc += er[e] * wr[e];
        }
        sM[v][h] = acc;
    }

    // W2 rows in registers (conflict-free layout): warp w owns logits w, w+8;
    // warp 0 additionally owns logit 16.
    float w2a[16], w2b[16], w2c[16];
#pragma unroll
    for (int k = 0; k < 16; k++) {
        w2a[k] = W2[(size_t)w * Hv + k * 32 + lane];
        w2b[k] = W2[(size_t)(w + 8) * Hv + k * 32 + lane];
    }
    const float biasA = b2[w];
    const float biasB = b2[w + 8];
    float biasC = 0.f;
    if (w == 0) {
#pragma unroll
        for (int k = 0; k < 16; k++)
            w2c[k] = W2[(size_t)16 * Hv + k * 32 + lane];
        biasC = b2[16];
    }
    __syncthreads();

    float* outL = out + OFF_LOGITS;
    float* outP = out + OFF_PREDS;

    const float* preB = g_pre + (size_t)b * Lv * Hv;

    float pc0 = preB[tid];
    float pc1 = preB[tid + 256];

    for (int t = 0; t < Lv; t++) {
        float pn0 = 0.f, pn1 = 0.f;
        if (t + 1 < Lv) {
            pn0 = preB[(size_t)(t + 1) * Hv + tid];
            pn1 = preB[(size_t)(t + 1) * Hv + tid + 256];
        }

        // stage A: every warp computes argmax of previous logits, then hidden
        int pred;
        if (t == 0) {
            pred = 0;   // PAD
        } else {
            pred = argmax17((lane < Vv) ? sLogit[lane] : 0.f, lane);
            if (tid == 0) outP[(size_t)b * Lv + (t - 1)] = (float)pred;
        }
        sH[tid]       = tanhf(pc0 + sM[pred][tid]);
        sH[tid + 256] = tanhf(pc1 + sM[pred][tid + 256]);
        __syncthreads();

        // stage B: warp w computes logits w and w+8 (warp 0 also 16)
        {
            float hv[16];
#pragma unroll
            for (int k = 0; k < 16; k++) hv[k] = sH[k * 32 + lane];

            float accA = 0.f, accB = 0.f;
#pragma unroll
            for (int k = 0; k < 16; k++) {
                accA += hv[k] * w2a[k];
                accB += hv[k] * w2b[k];
            }
            float accC = 0.f;
            if (w == 0) {
#pragma unroll
                for (int k = 0; k < 16; k++) accC += hv[k] * w2c[k];
            }
#pragma unroll
            for (int off = 16; off; off >>= 1) {
                accA += __shfl_xor_sync(FULLMASK, accA, off);
                accB += __shfl_xor_sync(FULLMASK, accB, off);
                accC += __shfl_xor_sync(FULLMASK, accC, off);
            }
            if (lane == 0) {
                float lgA = accA + biasA;
                float lgB = accB + biasB;
                sLogit[w]     = lgA;
                sLogit[w + 8] = lgB;
                const size_t base = ((size_t)b * Lv + t) * Vv;
                outL[base + w]     = lgA;
                outL[base + w + 8] = lgB;
                if (w == 0) {
                    float lgC = accC + biasC;
                    sLogit[16] = lgC;
                    outL[base + 16] = lgC;
                }
            }
        }
        __syncthreads();

        pc0 = pn0;
        pc1 = pn1;
    }

    // tail: argmax for the final timestep
    if (w == 0) {
        int pred = argmax17((lane < Vv) ? sLogit[lane] : 0.f, lane);
        if (lane == 0) outP[(size_t)b * Lv + (Lv - 1)] = (float)pred;
    }
}

// ---------------------------------------------------------------------------
// Kernel 3: parallel post-pass — log-softmax from saved logits, preds_emb.
// ---------------------------------------------------------------------------
__global__ __launch_bounds__(256) void post_kernel(
    const float* __restrict__ emb_table,
    float* __restrict__ out)
{
    const float* outL = out + OFF_LOGITS;
    const float* outP = out + OFF_PREDS;
    float* outQ  = out + OFF_PROBS;
    float* outEb = out + OFF_EMB;

    const int lane = threadIdx.x & 31;
    const int warps_total = (gridDim.x * blockDim.x) >> 5;
    int gw = (blockIdx.x * blockDim.x + threadIdx.x) >> 5;

    for (int row = gw; row < Bv * Lv; row += warps_total) {
        float v = (lane < Vv) ? outL[(size_t)row * Vv + lane] : -1e30f;
        float m = v;
#pragma unroll
        for (int off = 16; off; off >>= 1)
            m = fmaxf(m, __shfl_xor_sync(FULLMASK, m, off));
        float e = (lane < Vv) ? expf(v - m) : 0.f;
        float s = e;
#pragma unroll
        for (int off = 16; off; off >>= 1)
            s += __shfl_xor_sync(FULLMASK, s, off);
        float lse = m + logf(s);
        if (lane < Vv) outQ[(size_t)row * Vv + lane] = v - lse;

        int pred = (int)outP[row];
        float e0 = (pred != 0) ? emb_table[pred * Ev + lane] : 0.f;
        float e1 = (pred != 0) ? emb_table[pred * Ev + 32 + lane] : 0.f;
        outEb[(size_t)row * Ev + lane]      = e0;
        outEb[(size_t)row * Ev + 32 + lane] = e1;
    }
}

// ---------------------------------------------------------------------------
extern "C" void kernel_launch(void* const* d_in, const int* in_sizes, int n_in,
                              void* d_out, int out_size)
{
    const float* inputs    = (const float*)d_in[0];  // [B, L, D]
    const float* emb_table = (const float*)d_in[1];  // [V, E]
    const float* W1        = (const float*)d_in[2];  // [H, D+E]
    const float* b1        = (const float*)d_in[3];  // [H]
    const float* W2        = (const float*)d_in[4];  // [V, H]
    const float* b2        = (const float*)d_in[5];  // [V]
    float* out = (float*)d_out;

    (void)in_sizes; (void)n_in; (void)out_size;

    cudaFuncSetAttribute(gemm_mma_kernel,
                         cudaFuncAttributeMaxDynamicSharedMemorySize,
                         SM_TOT_BYTES);

    gemm_mma_kernel<<<2048, 256, SM_TOT_BYTES>>>(inputs, W1, b1);

    scan_kernel<<<Bv, 256>>>(emb_table, W1, W2, b2, out);

    post_kernel<<<256, 256>>>(emb_table, out);
}

// round 14
// speedup vs baseline: 2.0507x; 1.0224x over previous
#include <cuda_runtime.h>
#include <cuda_bf16.h>
#include <cstdint>
#include <math.h>

// Problem dims
#define Bv 128
#define Lv 512
#define Dv 512
#define Ev 64
#define Hv 512
#define Vv 17

#define FULLMASK 0xffffffffu

// Output layout (float32 concat of the 4 reference outputs)
#define OFF_LOGITS 0
#define OFF_PREDS  (Bv*Lv*Vv)                 // 1114112
#define OFF_PROBS  (OFF_PREDS + Bv*Lv)        // 1179648
#define OFF_EMB    (OFF_PROBS + Bv*Lv*Vv)     // 2293760

// Scratch: pre[b, t, h] = inputs[b,t,:] @ W1[:, :D]^T + b1   (128 MB)
__device__ float g_pre[(size_t)Bv * Lv * Hv];

// ---------------------------------------------------------------------------
__device__ __forceinline__ float lo_part(float x) {
    float h = __uint_as_float(__float_as_uint(x) & 0xFFFFE000u);
    return x - h;   // exact
}

__device__ __forceinline__ void mma_tf32(
    float* d, const uint32_t* a, const uint32_t* b)
{
    asm volatile(
        "mma.sync.aligned.m16n8k8.row.col.f32.tf32.tf32.f32 "
        "{%0,%1,%2,%3}, {%4,%5,%6,%7}, {%8,%9}, {%0,%1,%2,%3};\n"
        : "+f"(d[0]), "+f"(d[1]), "+f"(d[2]), "+f"(d[3])
        : "r"(a[0]), "r"(a[1]), "r"(a[2]), "r"(a[3]),
          "r"(b[0]), "r"(b[1]));
}

// dynamic smem layout in floats: A | B, 4096 floats each (32KB total), BK=32
#define F_A 0
#define F_B 4096
#define SM_TOT_BYTES (8192 * 4)

// ---------------------------------------------------------------------------
// Kernel 1: pre = A @ W1x^T + b1 via mma.sync tf32, 3-term precision split
// with hi/lo derived in registers.  Exact R10 configuration (634us).
// ---------------------------------------------------------------------------
__global__ __launch_bounds__(256) void gemm_mma_kernel(
    const float* __restrict__ A,      // [B*L, D]
    const float* __restrict__ W,      // [H, D+E]
    const float* __restrict__ bias)   // [H]
{
    extern __shared__ float sm[];

    const int tid  = threadIdx.x;
    const int w    = tid >> 5;
    const int lane = tid & 31;
    const int wm   = w >> 2;          // 0..1  (m offset 64)
    const int wn   = w & 3;           // 0..3  (n offset 32)

    const int bm = (blockIdx.x >> 2) * 128;   // row block in [B*L]
    const int bn = (blockIdx.x & 3) * 128;    // col block in [H]

    const int srow = tid >> 1;
    const int cgrp = (tid & 1) * 16;

    const float* aP = A + (size_t)(bm + srow) * Dv + cgrp;
    const float* wP = W + (size_t)(bn + srow) * (Dv + Ev) + cgrp;

    float acc[4][4][4];
#pragma unroll
    for (int i = 0; i < 4; i++)
#pragma unroll
        for (int j = 0; j < 4; j++)
#pragma unroll
            for (int r = 0; r < 4; r++) acc[i][j][r] = 0.f;

    const int a_mf  = srow >> 4;
    const int a_r16 = srow & 15;
    const int a_lb  = (a_r16 & 7) << 2;
    const int a_rb  = a_r16 >> 3;
    const int b_nf  = srow >> 3;
    const int b_lb  = (srow & 7) << 2;

    for (int ch = 0; ch < 16; ch++) {
        const int k0 = ch * 32;
#pragma unroll
        for (int q = 0; q < 4; q++) {
            const int kc = cgrp + q * 4;
            const int ks = kc >> 3;
            const int c8 = kc & 7;
            float4 av = *reinterpret_cast<const float4*>(aP + k0 + q * 4);
            float4 bv = *reinterpret_cast<const float4*>(wP + k0 + q * 4);
            {
                const int reg = a_rb + ((c8 >> 2) << 1);
                const int base = ((ks * 8 + a_mf) * 32 + a_lb + (c8 & 3)) * 4 + reg;
                sm[F_A + base]      = av.x;
                sm[F_A + base + 4]  = av.y;
                sm[F_A + base + 8]  = av.z;
                sm[F_A + base + 12] = av.w;
            }
            {
                const int reg = c8 >> 2;
                const int base = ((ks * 16 + b_nf) * 32 + b_lb + (c8 & 3)) * 2 + reg;
                sm[F_B + base]     = bv.x;
                sm[F_B + base + 2] = bv.y;
                sm[F_B + base + 4] = bv.z;
                sm[F_B + base + 6] = bv.w;
            }
        }
        __syncthreads();

#pragma unroll
        for (int ks = 0; ks < 4; ks++) {
            float    afr[4][4];
            uint32_t alo[4][4];
            float    bfr[4][2];
            uint32_t blo[4][2];
#pragma unroll
            for (int mf = 0; mf < 4; mf++) {
                const int mfg = wm * 4 + mf;
                const int ix = ((ks * 8 + mfg) * 32 + lane) * 4;
                *reinterpret_cast<float4*>(afr[mf]) =
                    *reinterpret_cast<const float4*>(&sm[F_A + ix]);
#pragma unroll
                for (int r = 0; r < 4; r++)
                    alo[mf][r] = __float_as_uint(lo_part(afr[mf][r]));
            }
#pragma unroll
            for (int nf = 0; nf < 4; nf++) {
                const int nfg = wn * 4 + nf;
                const int ix = ((ks * 16 + nfg) * 32 + lane) * 2;
                *reinterpret_cast<float2*>(bfr[nf]) =
                    *reinterpret_cast<const float2*>(&sm[F_B + ix]);
#pragma unroll
                for (int r = 0; r < 2; r++)
                    blo[nf][r] = __float_as_uint(lo_part(bfr[nf][r]));
            }
#pragma unroll
            for (int mf = 0; mf < 4; mf++)
#pragma unroll
                for (int nf = 0; nf < 4; nf++) {
                    const uint32_t* ahi =
                        reinterpret_cast<const uint32_t*>(afr[mf]);
                    const uint32_t* bhi =
                        reinterpret_cast<const uint32_t*>(bfr[nf]);
                    mma_tf32(acc[mf][nf], ahi, bhi);
                    mma_tf32(acc[mf][nf], ahi, blo[nf]);
                    mma_tf32(acc[mf][nf], alo[mf], bhi);
                }
        }
        __syncthreads();
    }

#pragma unroll
    for (int mf = 0; mf < 4; mf++) {
        const int row0 = bm + wm * 64 + mf * 16 + (lane >> 2);
#pragma unroll
        for (int nf = 0; nf < 4; nf++) {
            const int col0 = bn + wn * 32 + nf * 8 + 2 * (lane & 3);
            const float bb0 = bias[col0];
            const float bb1 = bias[col0 + 1];
            float2 v0, v1;
            v0.x = acc[mf][nf][0] + bb0;
            v0.y = acc[mf][nf][1] + bb1;
            v1.x = acc[mf][nf][2] + bb0;
            v1.y = acc[mf][nf][3] + bb1;
            *reinterpret_cast<float2*>(&g_pre[(size_t)row0 * Hv + col0]) = v0;
            *reinterpret_cast<float2*>(&g_pre[(size_t)(row0 + 8) * Hv + col0]) = v1;
        }
    }
}

// ---------------------------------------------------------------------------
// fast warp argmax over lanes [0, Vv): monotone-uint transform + redux.max +
// ballot + ffs.  Uniform across the warp; first-max tie-break (jnp.argmax).
// ---------------------------------------------------------------------------
__device__ __forceinline__ int argmax17(float v, int lane)
{
    unsigned u = __float_as_uint(v);
    u = (u & 0x80000000u) ? ~u : (u | 0x80000000u);
    if (lane >= Vv) u = 0u;
    unsigned mx = __reduce_max_sync(FULLMASK, u);
    unsigned msk = __ballot_sync(FULLMASK, u == mx);
    return __ffs(msk) - 1;
}

// ---------------------------------------------------------------------------
// Kernel 2: sequential scan. 1 CTA per batch element, 256 threads (8 warps).
// Each thread owns h-elements {tid, tid+256}. DEPTH-3 register-ring prefetch
// of g_pre so each DRAM load has ~3 steps of latency budget. Warp w computes
// logits {w, w+8} (warp 0 also 16). Softmax/embedding in post_kernel.
// ---------------------------------------------------------------------------
#define PFD 3   // prefetch depth

__global__ __launch_bounds__(256) void scan_kernel(
    const float* __restrict__ emb_table,   // [V, E]
    const float* __restrict__ W1,          // [H, D+E]
    const float* __restrict__ W2,          // [V, H]
    const float* __restrict__ b2,          // [V]
    float* __restrict__ out)
{
    __shared__ float sM[Vv][Hv];
    __shared__ float sH[Hv];
    __shared__ float sLogit[20];

    const int b    = blockIdx.x;
    const int tid  = threadIdx.x;
    const int w    = tid >> 5;
    const int lane = tid & 31;

    for (int idx = tid; idx < Vv * Hv; idx += 256) {
        int v = idx / Hv, h = idx - v * Hv;
        float acc = 0.f;
        if (v != 0) {
            const float* er = emb_table + v * Ev;
            const float* wr = W1 + (size_t)h * (Dv + Ev) + Dv;
#pragma unroll 8
            for (int e = 0; e < Ev; e++) acc += er[e] * wr[e];
        }
        sM[v][h] = acc;
    }

    // W2 rows in registers: warp w owns logits w, w+8; warp 0 also 16.
    float w2a[16], w2b[16], w2c[16];
#pragma unroll
    for (int k = 0; k < 16; k++) {
        w2a[k] = W2[(size_t)w * Hv + k * 32 + lane];
        w2b[k] = W2[(size_t)(w + 8) * Hv + k * 32 + lane];
    }
    const float biasA = b2[w];
    const float biasB = b2[w + 8];
    float biasC = 0.f;
    if (w == 0) {
#pragma unroll
        for (int k = 0; k < 16; k++)
            w2c[k] = W2[(size_t)16 * Hv + k * 32 + lane];
        biasC = b2[16];
    }
    __syncthreads();

    float* outL = out + OFF_LOGITS;
    float* outP = out + OFF_PREDS;

    const float* preB = g_pre + (size_t)b * Lv * Hv;

    // depth-3 register ring for the pre stream
    float buf0[PFD], buf1[PFD];
#pragma unroll
    for (int i = 0; i < PFD; i++) {
        buf0[i] = preB[(size_t)i * Hv + tid];
        buf1[i] = preB[(size_t)i * Hv + tid + 256];
    }

#pragma unroll 3
    for (int t = 0; t < Lv; t++) {
        const int slot = t % PFD;
        const float cur0 = buf0[slot];        // waits on load issued at t-PFD
        const float cur1 = buf1[slot];
        // refill the freed slot with t+PFD (issued PFD steps ahead of use)
        if (t + PFD < Lv) {
            buf0[slot] = preB[(size_t)(t + PFD) * Hv + tid];
            buf1[slot] = preB[(size_t)(t + PFD) * Hv + tid + 256];
        }

        // stage A: every warp computes argmax of previous logits, then hidden
        int pred;
        if (t == 0) {
            pred = 0;   // PAD
        } else {
            pred = argmax17((lane < Vv) ? sLogit[lane] : 0.f, lane);
            if (tid == 0) outP[(size_t)b * Lv + (t - 1)] = (float)pred;
        }
        sH[tid]       = tanhf(cur0 + sM[pred][tid]);
        sH[tid + 256] = tanhf(cur1 + sM[pred][tid + 256]);
        __syncthreads();

        // stage B: warp w computes logits w and w+8 (warp 0 also 16)
        {
            float hv[16];
#pragma unroll
            for (int k = 0; k < 16; k++) hv[k] = sH[k * 32 + lane];

            float accA = 0.f, accB = 0.f;
#pragma unroll
            for (int k = 0; k < 16; k++) {
                accA += hv[k] * w2a[k];
                accB += hv[k] * w2b[k];
            }
            float accC = 0.f;
            if (w == 0) {
#pragma unroll
                for (int k = 0; k < 16; k++) accC += hv[k] * w2c[k];
            }
#pragma unroll
            for (int off = 16; off; off >>= 1) {
                accA += __shfl_xor_sync(FULLMASK, accA, off);
                accB += __shfl_xor_sync(FULLMASK, accB, off);
                accC += __shfl_xor_sync(FULLMASK, accC, off);
            }
            if (lane == 0) {
                float lgA = accA + biasA;
                float lgB = accB + biasB;
                sLogit[w]     = lgA;
                sLogit[w + 8] = lgB;
                const size_t base = ((size_t)b * Lv + t) * Vv;
                outL[base + w]     = lgA;
                outL[base + w + 8] = lgB;
                if (w == 0) {
                    float lgC = accC + biasC;
                    sLogit[16] = lgC;
                    outL[base + 16] = lgC;
                }
            }
        }
        __syncthreads();
    }

    // tail: argmax for the final timestep
    if (w == 0) {
        int pred = argmax17((lane < Vv) ? sLogit[lane] : 0.f, lane);
        if (lane == 0) outP[(size_t)b * Lv + (Lv - 1)] = (float)pred;
    }
}

// ---------------------------------------------------------------------------
// Kernel 3: parallel post-pass — log-softmax from saved logits, preds_emb.
// ---------------------------------------------------------------------------
__global__ __launch_bounds__(256) void post_kernel(
    const float* __restrict__ emb_table,
    float* __restrict__ out)
{
    const float* outL = out + OFF_LOGITS;
    const float* outP = out + OFF_PREDS;
    float* outQ  = out + OFF_PROBS;
    float* outEb = out + OFF_EMB;

    const int lane = threadIdx.x & 31;
    const int warps_total = (gridDim.x * blockDim.x) >> 5;
    int gw = (blockIdx.x * blockDim.x + threadIdx.x) >> 5;

    for (int row = gw; row < Bv * Lv; row += warps_total) {
        float v = (lane < Vv) ? outL[(size_t)row * Vv + lane] : -1e30f;
        float m = v;
#pragma unroll
        for (int off = 16; off; off >>= 1)
            m = fmaxf(m, __shfl_xor_sync(FULLMASK, m, off));
        float e = (lane < Vv) ? expf(v - m) : 0.f;
        float s = e;
#pragma unroll
        for (int off = 16; off; off >>= 1)
            s += __shfl_xor_sync(FULLMASK, s, off);
        float lse = m + logf(s);
        if (lane < Vv) outQ[(size_t)row * Vv + lane] = v - lse;

        int pred = (int)outP[row];
        float e0 = (pred != 0) ? emb_table[pred * Ev + lane] : 0.f;
        float e1 = (pred != 0) ? emb_table[pred * Ev + 32 + lane] : 0.f;
        outEb[(size_t)row * Ev + lane]      = e0;
        outEb[(size_t)row * Ev + 32 + lane] = e1;
    }
}

// ---------------------------------------------------------------------------
extern "C" void kernel_launch(void* const* d_in, const int* in_sizes, int n_in,
                              void* d_out, int out_size)
{
    const float* inputs    = (const float*)d_in[0];  // [B, L, D]
    const float* emb_table = (const float*)d_in[1];  // [V, E]
    const float* W1        = (const float*)d_in[2];  // [H, D+E]
    const float* b1        = (const float*)d_in[3];  // [H]
    const float* W2        = (const float*)d_in[4];  // [V, H]
    const float* b2        = (const float*)d_in[5];  // [V]
    float* out = (float*)d_out;

    (void)in_sizes; (void)n_in; (void)out_size;

    cudaFuncSetAttribute(gemm_mma_kernel,
                         cudaFuncAttributeMaxDynamicSharedMemorySize,
                         SM_TOT_BYTES);

    gemm_mma_kernel<<<2048, 256, SM_TOT_BYTES>>>(inputs, W1, b1);

    scan_kernel<<<Bv, 256>>>(emb_table, W1, W2, b2, out);

    post_kernel<<<256, 256>>>(emb_table, out);
}